// round 3
// baseline (speedup 1.0000x reference)
#include <cuda_runtime.h>

#define B_  2
#define Q_  2048
#define S_  2048
#define D_  1024
#define H_  16
#define AD_ 64

// Scratch (device globals — no allocations allowed)
__device__ float g_rq[(size_t)B_ * Q_ * D_];        // (b,q,h,a)
__device__ float g_kv[(size_t)B_ * S_ * 2 * D_];    // (b,s,[k|v],h,a)
__device__ float g_o [(size_t)B_ * Q_ * D_];        // (b,q,h,a)
__device__ unsigned char g_mask8[(size_t)B_ * Q_ * S_];  // packed bool mask

// ---------------------------------------------------------------------------
// Pack int32 mask -> uint8 (harness delivers jax bool as int32).
// ---------------------------------------------------------------------------
__global__ void pack_mask(const int* __restrict__ m32)
{
    const size_t n16 = (size_t)B_ * Q_ * S_ / 16;
    size_t i = blockIdx.x * blockDim.x + threadIdx.x;
    if (i >= n16) return;
    const int4* src = (const int4*)m32 + i * 4;
    unsigned long long lo = 0, hi = 0;
    #pragma unroll
    for (int p = 0; p < 2; p++) {
        int4 a = src[p * 2 + 0];
        int4 b = src[p * 2 + 1];
        unsigned long long w = 0;
        w |= (unsigned long long)(a.x != 0) << 0;
        w |= (unsigned long long)(a.y != 0) << 8;
        w |= (unsigned long long)(a.z != 0) << 16;
        w |= (unsigned long long)(a.w != 0) << 24;
        w |= (unsigned long long)(b.x != 0) << 32;
        w |= (unsigned long long)(b.y != 0) << 40;
        w |= (unsigned long long)(b.z != 0) << 48;
        w |= (unsigned long long)(b.w != 0) << 56;
        if (p == 0) lo = w; else hi = w;
    }
    ((ulonglong2*)g_mask8)[i] = make_ulonglong2(lo, hi);
}

// ---------------------------------------------------------------------------
// Generic TN SGEMM: C[M,N] = A[M,K] @ Bm[N,K]^T, all row-major.
// M,N multiples of 128; K multiple of 16. 256 threads, 8x8 micro-tile.
// ---------------------------------------------------------------------------
__global__ __launch_bounds__(256, 2)
void sgemm_tn(const float* __restrict__ A, const float* __restrict__ Bm,
              float* __restrict__ C, int M, int N, int K)
{
    __shared__ float As[16][132];   // As[k][m]
    __shared__ float Bs[16][132];   // Bs[k][n]

    const int tid = threadIdx.x;
    const int m0 = blockIdx.y * 128;
    const int n0 = blockIdx.x * 128;
    const int ty = tid >> 4;        // 0..15 -> m micro row
    const int tx = tid & 15;        // 0..15 -> n micro col

    float acc[8][8];
    #pragma unroll
    for (int i = 0; i < 8; i++)
        #pragma unroll
        for (int j = 0; j < 8; j++) acc[i][j] = 0.f;

    for (int kt = 0; kt < K; kt += 16) {
        #pragma unroll
        for (int p = 0; p < 2; p++) {
            int f   = tid + p * 256;       // 0..511
            int row = f >> 2;              // 0..127
            int kq  = f & 3;               // float4 index within 16-k slab
            float4 va = *(const float4*)(A + (size_t)(m0 + row) * K + kt + kq * 4);
            As[kq * 4 + 0][row] = va.x;
            As[kq * 4 + 1][row] = va.y;
            As[kq * 4 + 2][row] = va.z;
            As[kq * 4 + 3][row] = va.w;
            float4 vb = *(const float4*)(Bm + (size_t)(n0 + row) * K + kt + kq * 4);
            Bs[kq * 4 + 0][row] = vb.x;
            Bs[kq * 4 + 1][row] = vb.y;
            Bs[kq * 4 + 2][row] = vb.z;
            Bs[kq * 4 + 3][row] = vb.w;
        }
        __syncthreads();

        #pragma unroll
        for (int k = 0; k < 16; k++) {
            float a[8], b[8];
            *(float4*)(a)     = *(const float4*)&As[k][ty * 8];
            *(float4*)(a + 4) = *(const float4*)&As[k][ty * 8 + 4];
            *(float4*)(b)     = *(const float4*)&Bs[k][tx * 8];
            *(float4*)(b + 4) = *(const float4*)&Bs[k][tx * 8 + 4];
            #pragma unroll
            for (int i = 0; i < 8; i++)
                #pragma unroll
                for (int j = 0; j < 8; j++)
                    acc[i][j] = fmaf(a[i], b[j], acc[i][j]);
        }
        __syncthreads();
    }

    #pragma unroll
    for (int i = 0; i < 8; i++) {
        float* cp = C + (size_t)(m0 + ty * 8 + i) * N + n0 + tx * 8;
        *(float4*)(cp)     = make_float4(acc[i][0], acc[i][1], acc[i][2], acc[i][3]);
        *(float4*)(cp + 4) = make_float4(acc[i][4], acc[i][5], acc[i][6], acc[i][7]);
    }
}

// ---------------------------------------------------------------------------
// Fused attention: per (b,h), 128-q tile per block, stream S in 64-wide tiles.
// t = relu(score/8 + nbias)^2 (0 where masked). Accumulate num = sum t*V and
// den = sum t; divide once at the end (sparse_norm is linear — no softmax
// rescaling needed).
// ---------------------------------------------------------------------------
#define QS_ 132                    // padded stride for q-indexed smem rows
#define SS_ 68                     // padded stride for s/a-indexed smem rows
#define SMEM_ATTN ((64 * QS_ + 64 * SS_ + 64 * SS_ + 64 * QS_ + 128) * 4)

__global__ __launch_bounds__(256, 2)
void attn_kernel(const float* __restrict__ nbias)
{
    extern __shared__ float sm[];
    float* Qs  = sm;                 // [64 k][132]  Qs[k][q]
    float* Ks  = Qs + 64 * QS_;      // [64 k][68]   Ks[k][s]
    float* Vs  = Ks + 64 * SS_;      // [64 s][68]   Vs[s][a]
    float* Tt  = Vs + 64 * SS_;      // [64 s][132]  Tt[s][q]
    float* den = Tt + 64 * QS_;      // [128]

    const int tid = threadIdx.x;
    const int b   = blockIdx.y >> 4;
    const int h   = blockIdx.y & 15;
    const int q0  = blockIdx.x * 128;
    const float nb = nbias[0];

    const float* rq = g_rq + ((size_t)(b * Q_ + q0)) * D_ + h * AD_;
    const float* rk = g_kv + (size_t)b * S_ * 2048 + h * AD_;
    const float* rv = rk + 1024;
    const unsigned char* mbase = g_mask8 + (size_t)(b * Q_ + q0) * S_;

    // Load Q tile (128 x 64), transposed into Qs[k][q]
    #pragma unroll
    for (int p = 0; p < 8; p++) {
        int f   = tid + p * 256;      // 0..2047
        int row = f >> 4;             // q row 0..127
        int k4  = f & 15;             // float4 index along k
        float4 v = *(const float4*)(rq + (size_t)row * D_ + k4 * 4);
        Qs[(k4 * 4 + 0) * QS_ + row] = v.x;
        Qs[(k4 * 4 + 1) * QS_ + row] = v.y;
        Qs[(k4 * 4 + 2) * QS_ + row] = v.z;
        Qs[(k4 * 4 + 3) * QS_ + row] = v.w;
    }
    if (tid < 128) den[tid] = 0.f;

    const int tq = tid & 31;          // 32 groups over q (4 rows each)
    const int tg = tid >> 5;          // 8 groups over s (phase A) / a (phase B)

    float acc[4][8];
    #pragma unroll
    for (int i = 0; i < 4; i++)
        #pragma unroll
        for (int j = 0; j < 8; j++) acc[i][j] = 0.f;

    for (int s0 = 0; s0 < S_; s0 += 64) {
        // Load K (transposed -> Ks[k][s]) and V (natural -> Vs[s][a])
        #pragma unroll
        for (int p = 0; p < 4; p++) {
            int f   = tid + p * 256;   // 0..1023
            int row = f >> 4;          // s row 0..63
            int k4  = f & 15;
            float4 kk = *(const float4*)(rk + (size_t)(s0 + row) * 2048 + k4 * 4);
            Ks[(k4 * 4 + 0) * SS_ + row] = kk.x;
            Ks[(k4 * 4 + 1) * SS_ + row] = kk.y;
            Ks[(k4 * 4 + 2) * SS_ + row] = kk.z;
            Ks[(k4 * 4 + 3) * SS_ + row] = kk.w;
            float4 vv = *(const float4*)(rv + (size_t)(s0 + row) * 2048 + k4 * 4);
            *(float4*)(Vs + row * SS_ + k4 * 4) = vv;
        }
        __syncthreads();

        // Phase A: scores for 4q x 8s micro-tile
        float sacc[4][8];
        #pragma unroll
        for (int i = 0; i < 4; i++)
            #pragma unroll
            for (int j = 0; j < 8; j++) sacc[i][j] = 0.f;

        #pragma unroll 8
        for (int k = 0; k < 64; k++) {
            float4 qa = *(const float4*)(Qs + k * QS_ + tq * 4);
            float4 k0 = *(const float4*)(Ks + k * SS_ + tg * 8);
            float4 k1 = *(const float4*)(Ks + k * SS_ + tg * 8 + 4);
            float qf[4] = {qa.x, qa.y, qa.z, qa.w};
            float kf[8] = {k0.x, k0.y, k0.z, k0.w, k1.x, k1.y, k1.z, k1.w};
            #pragma unroll
            for (int i = 0; i < 4; i++)
                #pragma unroll
                for (int j = 0; j < 8; j++)
                    sacc[i][j] = fmaf(qf[i], kf[j], sacc[i][j]);
        }

        // mask + relu^2, write Tt[s][q]
        unsigned long long mr[4];
        #pragma unroll
        for (int i = 0; i < 4; i++)
            mr[i] = *(const unsigned long long*)(mbase + (size_t)(tq * 4 + i) * S_ + s0 + tg * 8);

        #pragma unroll
        for (int j = 0; j < 8; j++) {
            float tw[4];
            #pragma unroll
            for (int i = 0; i < 4; i++) {
                float sc = fmaxf(fmaf(sacc[i][j], 0.125f, nb), 0.f);
                float t  = sc * sc;
                if ((mr[i] >> (8 * j)) & 0xFFull) t = 0.f;   // mask true -> dropped
                tw[i] = t;
            }
            *(float4*)(Tt + (tg * 8 + j) * QS_ + tq * 4) =
                make_float4(tw[0], tw[1], tw[2], tw[3]);
        }
        __syncthreads();

        // Denominator partials (threads 0..127, one q row each)
        if (tid < 128) {
            float s = 0.f;
            #pragma unroll 16
            for (int si = 0; si < 64; si++) s += Tt[si * QS_ + tid];
            den[tid] += s;
        }

        // Phase B: num += T @ V   (4q x 8a micro-tile)
        #pragma unroll 8
        for (int si = 0; si < 64; si++) {
            float4 ta = *(const float4*)(Tt + si * QS_ + tq * 4);
            float4 v0 = *(const float4*)(Vs + si * SS_ + tg * 8);
            float4 v1 = *(const float4*)(Vs + si * SS_ + tg * 8 + 4);
            float tf[4] = {ta.x, ta.y, ta.z, ta.w};
            float vf[8] = {v0.x, v0.y, v0.z, v0.w, v1.x, v1.y, v1.z, v1.w};
            #pragma unroll
            for (int i = 0; i < 4; i++)
                #pragma unroll
                for (int j = 0; j < 8; j++)
                    acc[i][j] = fmaf(tf[i], vf[j], acc[i][j]);
        }
        __syncthreads();   // protects den (final read) and Ks/Vs/Tt reuse
    }

    // Final divide + store
    float* op = g_o + ((size_t)(b * Q_ + q0)) * D_ + h * AD_ + tg * 8;
    #pragma unroll
    for (int i = 0; i < 4; i++) {
        int q = tq * 4 + i;
        float inv = 1.f / (den[q] + 1e-32f);
        float* p = op + (size_t)q * D_;
        *(float4*)(p)     = make_float4(acc[i][0] * inv, acc[i][1] * inv,
                                        acc[i][2] * inv, acc[i][3] * inv);
        *(float4*)(p + 4) = make_float4(acc[i][4] * inv, acc[i][5] * inv,
                                        acc[i][6] * inv, acc[i][7] * inv);
    }
}

// ---------------------------------------------------------------------------
extern "C" void kernel_launch(void* const* d_in, const int* in_sizes, int n_in,
                              void* d_out, int out_size)
{
    const float* iQ    = (const float*)d_in[0];
    const float* iK    = (const float*)d_in[1];
    const int*   mask  = (const int*)d_in[2];       // jax bool -> int32
    const float* Wq    = (const float*)d_in[3];
    const float* Wkv   = (const float*)d_in[4];
    const float* Wo    = (const float*)d_in[5];
    const float* nbias = (const float*)d_in[6];
    float*       out   = (float*)d_out;

    float *rq, *kv, *o;
    cudaGetSymbolAddress((void**)&rq, g_rq);
    cudaGetSymbolAddress((void**)&kv, g_kv);
    cudaGetSymbolAddress((void**)&o,  g_o);

    cudaFuncSetAttribute(attn_kernel,
                         cudaFuncAttributeMaxDynamicSharedMemorySize, SMEM_ATTN);

    // 0) pack int32 mask -> uint8
    {
        size_t n16 = (size_t)B_ * Q_ * S_ / 16;
        pack_mask<<<(unsigned)((n16 + 255) / 256), 256>>>(mask);
    }
    // 1) rq = iQ @ Wq^T               (4096 x 1024 x 1024)
    sgemm_tn<<<dim3(D_ / 128, (B_ * Q_) / 128), 256>>>(iQ, Wq, rq, B_ * Q_, D_, D_);
    // 2) kv = iK @ Wkv^T              (4096 x 2048 x 1024)
    sgemm_tn<<<dim3(2 * D_ / 128, (B_ * S_) / 128), 256>>>(iK, Wkv, kv, B_ * S_, 2 * D_, D_);
    // 3) fused masked relu^2 attention
    attn_kernel<<<dim3(Q_ / 128, B_ * H_), 256, SMEM_ATTN>>>(nbias);
    // 4) out = o @ Wo^T               (4096 x 1024 x 1024)
    sgemm_tn<<<dim3(D_ / 128, (B_ * Q_) / 128), 256>>>(o, Wo, out, B_ * Q_, D_, D_);
}

// round 4
// speedup vs baseline: 4.4197x; 4.4197x over previous
#include <cuda_runtime.h>
#include <cuda_fp16.h>
#include <cstdint>

#define B_  2
#define Q_  2048
#define S_  2048
#define D_  1024
#define H_  16
#define AD_ 64

// ---------------- scratch (device globals; no allocation allowed) ----------
__device__ __half g_hiQ [(size_t)B_ * Q_ * D_];
__device__ __half g_hiK [(size_t)B_ * S_ * D_];
__device__ __half g_hWq [(size_t)D_ * D_];
__device__ __half g_hWkv[(size_t)2 * D_ * D_];
__device__ __half g_hWo [(size_t)D_ * D_];
__device__ __half g_rq  [(size_t)B_ * Q_ * D_];        // (b,q,h,a) fp16
__device__ __half g_kv  [(size_t)B_ * S_ * 2 * D_];    // (b,s,[k|v],h,a) fp16
__device__ __half g_o   [(size_t)B_ * Q_ * D_];        // attention out fp16
__device__ unsigned char g_mask8[(size_t)B_ * Q_ * S_];

// ---------------- small utility kernels ------------------------------------
__global__ void pack_mask(const int* __restrict__ m32)
{
    const size_t n16 = (size_t)B_ * Q_ * S_ / 16;
    size_t i = blockIdx.x * (size_t)blockDim.x + threadIdx.x;
    if (i >= n16) return;
    const int4* src = (const int4*)m32 + i * 4;
    unsigned long long w[2];
    #pragma unroll
    for (int p = 0; p < 2; p++) {
        int4 a = src[p * 2 + 0];
        int4 b = src[p * 2 + 1];
        unsigned long long v = 0;
        v |= (unsigned long long)(a.x != 0) << 0;
        v |= (unsigned long long)(a.y != 0) << 8;
        v |= (unsigned long long)(a.z != 0) << 16;
        v |= (unsigned long long)(a.w != 0) << 24;
        v |= (unsigned long long)(b.x != 0) << 32;
        v |= (unsigned long long)(b.y != 0) << 40;
        v |= (unsigned long long)(b.z != 0) << 48;
        v |= (unsigned long long)(b.w != 0) << 56;
        w[p] = v;
    }
    ((ulonglong2*)g_mask8)[i] = make_ulonglong2(w[0], w[1]);
}

__global__ void f32_to_f16(const float* __restrict__ src, __half* __restrict__ dst,
                           size_t n8)
{
    size_t i = blockIdx.x * (size_t)blockDim.x + threadIdx.x;
    if (i >= n8) return;
    const float4* s = (const float4*)src + i * 2;
    float4 a = s[0], b = s[1];
    __half2 h0 = __floats2half2_rn(a.x, a.y);
    __half2 h1 = __floats2half2_rn(a.z, a.w);
    __half2 h2 = __floats2half2_rn(b.x, b.y);
    __half2 h3 = __floats2half2_rn(b.z, b.w);
    uint4 o;
    o.x = *(unsigned*)&h0; o.y = *(unsigned*)&h1;
    o.z = *(unsigned*)&h2; o.w = *(unsigned*)&h3;
    ((uint4*)dst)[i] = o;
}

// ---------------- mma/ldmatrix primitives ----------------------------------
__device__ __forceinline__ unsigned sptr(const void* p)
{
    return (unsigned)__cvta_generic_to_shared(p);
}
__device__ __forceinline__ void ldsm4(unsigned* r, unsigned a)
{
    asm volatile("ldmatrix.sync.aligned.m8n8.x4.shared.b16 {%0,%1,%2,%3}, [%4];"
                 : "=r"(r[0]), "=r"(r[1]), "=r"(r[2]), "=r"(r[3]) : "r"(a));
}
__device__ __forceinline__ void ldsm2(unsigned* r, unsigned a)
{
    asm volatile("ldmatrix.sync.aligned.m8n8.x2.shared.b16 {%0,%1}, [%2];"
                 : "=r"(r[0]), "=r"(r[1]) : "r"(a));
}
__device__ __forceinline__ void ldsm2t(unsigned* r, unsigned a)
{
    asm volatile("ldmatrix.sync.aligned.m8n8.x2.trans.shared.b16 {%0,%1}, [%2];"
                 : "=r"(r[0]), "=r"(r[1]) : "r"(a));
}
__device__ __forceinline__ void mma16816(float* d, const unsigned* a,
                                         const unsigned* b, const float* c)
{
    asm volatile(
        "mma.sync.aligned.m16n8k16.row.col.f32.f16.f16.f32 "
        "{%0,%1,%2,%3}, {%4,%5,%6,%7}, {%8,%9}, {%10,%11,%12,%13};"
        : "=f"(d[0]), "=f"(d[1]), "=f"(d[2]), "=f"(d[3])
        : "r"(a[0]), "r"(a[1]), "r"(a[2]), "r"(a[3]),
          "r"(b[0]), "r"(b[1]),
          "f"(c[0]), "f"(c[1]), "f"(c[2]), "f"(c[3]));
}

// ---------------------------------------------------------------------------
// HGEMM TN: C[M,N] = A[M,K] @ Bm[N,K]^T.  A,Bm fp16 row-major, C fp32 or fp16.
// BM=BN=128, BK=32, 256 threads, warp grid 2x4 (warp tile 64x32).
// ---------------------------------------------------------------------------
#define GS_ 40   // smem stride (halves); 80B -> conflict-free ldmatrix
template <typename OutT>
__global__ __launch_bounds__(256)
void hgemm_tn(const __half* __restrict__ A, const __half* __restrict__ Bm,
              OutT* __restrict__ C, int M, int N, int K)
{
    __shared__ __half As[128 * GS_];
    __shared__ __half Bs[128 * GS_];

    const int tid  = threadIdx.x;
    const int wid  = tid >> 5;
    const int lane = tid & 31;
    const int m0 = blockIdx.y * 128;
    const int n0 = blockIdx.x * 128;
    const int wm = (wid >> 2) * 64;   // {0,64}
    const int wn = (wid & 3) * 32;    // {0,32,64,96}
    const int r = lane >> 2, c = lane & 3;
    const int l16 = lane & 15;

    float acc[4][4][4];
    #pragma unroll
    for (int i = 0; i < 4; i++)
        #pragma unroll
        for (int j = 0; j < 4; j++)
            #pragma unroll
            for (int k = 0; k < 4; k++) acc[i][j][k] = 0.f;

    for (int kt = 0; kt < K; kt += 32) {
        #pragma unroll
        for (int p = 0; p < 2; p++) {
            int f   = tid + p * 256;       // 0..511
            int row = f >> 2;
            int c4  = f & 3;               // uint4 (8 halves) index
            *(uint4*)(As + row * GS_ + c4 * 8) =
                *(const uint4*)(A + (size_t)(m0 + row) * K + kt + c4 * 8);
            *(uint4*)(Bs + row * GS_ + c4 * 8) =
                *(const uint4*)(Bm + (size_t)(n0 + row) * K + kt + c4 * 8);
        }
        __syncthreads();

        #pragma unroll
        for (int kk = 0; kk < 32; kk += 16) {
            unsigned af[4][4];
            #pragma unroll
            for (int mi = 0; mi < 4; mi++) {
                unsigned a = sptr(As + (wm + mi * 16 + l16) * GS_ + kk + ((lane >> 4) << 3));
                ldsm4(af[mi], a);
            }
            unsigned bf[4][2];
            #pragma unroll
            for (int nj = 0; nj < 4; nj++) {
                // B operand from [n][k] source: non-trans x2
                unsigned a = sptr(Bs + (wn + nj * 8 + (l16 & 7)) * GS_ + kk + ((l16 >> 3) << 3));
                ldsm2(bf[nj], a);
            }
            #pragma unroll
            for (int mi = 0; mi < 4; mi++)
                #pragma unroll
                for (int nj = 0; nj < 4; nj++)
                    mma16816(acc[mi][nj], af[mi], bf[nj], acc[mi][nj]);
        }
        __syncthreads();
    }

    #pragma unroll
    for (int mi = 0; mi < 4; mi++) {
        #pragma unroll
        for (int nj = 0; nj < 4; nj++) {
            int row = m0 + wm + mi * 16 + r;
            int col = n0 + wn + nj * 8 + 2 * c;
            if (sizeof(OutT) == 4) {
                float* cp = (float*)C;
                *(float2*)(cp + (size_t)row * N + col) =
                    make_float2(acc[mi][nj][0], acc[mi][nj][1]);
                *(float2*)(cp + (size_t)(row + 8) * N + col) =
                    make_float2(acc[mi][nj][2], acc[mi][nj][3]);
            } else {
                __half* cp = (__half*)C;
                __half2 h0 = __floats2half2_rn(acc[mi][nj][0], acc[mi][nj][1]);
                __half2 h1 = __floats2half2_rn(acc[mi][nj][2], acc[mi][nj][3]);
                *(__half2*)(cp + (size_t)row * N + col) = h0;
                *(__half2*)(cp + (size_t)(row + 8) * N + col) = h1;
            }
        }
    }
}

// ---------------------------------------------------------------------------
// Fused attention, tensor-core version.
// Per block: one (b,h), 128 q rows. 8 warps x 16 q-rows. s streamed 64/iter.
// t = relu(score/8+nb)^2, zeroed by mask; num/den accumulated, divide at end.
// ---------------------------------------------------------------------------
#define AS_ 88   // smem stride (halves); 176B -> conflict-free ldmatrix

__global__ __launch_bounds__(256)
void attn_kernel(const float* __restrict__ nbias)
{
    __shared__ __half Qs[128 * AS_];
    __shared__ __half Ks[64 * AS_];
    __shared__ __half Vs[64 * AS_];

    const int tid  = threadIdx.x;
    const int wid  = tid >> 5;
    const int lane = tid & 31;
    const int l16  = lane & 15;
    const int r = lane >> 2, c = lane & 3;
    const int b  = blockIdx.y >> 4;
    const int h  = blockIdx.y & 15;
    const int q0 = blockIdx.x * 128;
    const float nb = nbias[0];

    const __half* rqp = g_rq + ((size_t)(b * Q_ + q0)) * D_ + h * AD_;
    const __half* kbase = g_kv + (size_t)b * S_ * 2 * D_ + h * AD_;   // stride 2048
    const __half* vbase = kbase + D_;
    const unsigned char* mrow0 = g_mask8 + (size_t)(b * Q_ + q0 + wid * 16 + r) * S_;
    const unsigned char* mrow8 = mrow0 + 8 * (size_t)S_;

    // load Q tile (128 x 64 halves)
    #pragma unroll
    for (int p = 0; p < 4; p++) {
        int f = tid + p * 256;       // 0..1023
        int row = f >> 3, c8 = f & 7;
        *(uint4*)(Qs + row * AS_ + c8 * 8) =
            *(const uint4*)(rqp + (size_t)row * D_ + c8 * 8);
    }
    __syncthreads();

    // Q fragments: 1 m16 tile per warp, 4 k16 steps (persistent)
    unsigned qf[4][4];
    #pragma unroll
    for (int k16 = 0; k16 < 4; k16++) {
        unsigned a = sptr(Qs + (wid * 16 + l16) * AS_ + k16 * 16 + ((lane >> 4) << 3));
        ldsm4(qf[k16], a);
    }

    float acc[8][4];
    #pragma unroll
    for (int j = 0; j < 8; j++)
        #pragma unroll
        for (int k = 0; k < 4; k++) acc[j][k] = 0.f;
    float den0 = 0.f, den1 = 0.f;

    for (int s0 = 0; s0 < S_; s0 += 64) {
        __syncthreads();   // previous iteration's reads done before overwrite
        #pragma unroll
        for (int p = 0; p < 2; p++) {
            int f = tid + p * 256;   // 0..511
            int row = f >> 3, c8 = f & 7;
            *(uint4*)(Ks + row * AS_ + c8 * 8) =
                *(const uint4*)(kbase + (size_t)(s0 + row) * 2048 + c8 * 8);
            *(uint4*)(Vs + row * AS_ + c8 * 8) =
                *(const uint4*)(vbase + (size_t)(s0 + row) * 2048 + c8 * 8);
        }
        __syncthreads();

        // ---- scores: 16q x 64s per warp --------------------------------
        float sc[8][4];
        #pragma unroll
        for (int j = 0; j < 8; j++)
            #pragma unroll
            for (int k = 0; k < 4; k++) sc[j][k] = 0.f;

        #pragma unroll
        for (int k16 = 0; k16 < 4; k16++) {
            #pragma unroll
            for (int j = 0; j < 8; j++) {
                unsigned bf[2];
                // K source [s][d] = [n][k] -> non-trans x2
                unsigned a = sptr(Ks + (j * 8 + (l16 & 7)) * AS_ + k16 * 16 + ((l16 >> 3) << 3));
                ldsm2(bf, a);
                mma16816(sc[j], qf[k16], bf, sc[j]);
            }
        }

        // ---- mask + relu^2 + den + pack P -------------------------------
        unsigned p0[8], p1[8];
        #pragma unroll
        for (int j = 0; j < 8; j++) {
            int scol = s0 + j * 8 + 2 * c;
            uchar2 m0 = *(const uchar2*)(mrow0 + scol);
            uchar2 m8 = *(const uchar2*)(mrow8 + scol);
            float t00 = fmaxf(fmaf(sc[j][0], 0.125f, nb), 0.f); t00 *= t00;
            float t01 = fmaxf(fmaf(sc[j][1], 0.125f, nb), 0.f); t01 *= t01;
            float t10 = fmaxf(fmaf(sc[j][2], 0.125f, nb), 0.f); t10 *= t10;
            float t11 = fmaxf(fmaf(sc[j][3], 0.125f, nb), 0.f); t11 *= t11;
            if (m0.x) t00 = 0.f;
            if (m0.y) t01 = 0.f;
            if (m8.x) t10 = 0.f;
            if (m8.y) t11 = 0.f;
            den0 += t00 + t01;
            den1 += t10 + t11;
            __half2 h0 = __floats2half2_rn(t00, t01);
            __half2 h1 = __floats2half2_rn(t10, t11);
            p0[j] = *(unsigned*)&h0;
            p1[j] = *(unsigned*)&h1;
        }

        // ---- num += P @ V ----------------------------------------------
        #pragma unroll
        for (int k16 = 0; k16 < 4; k16++) {
            unsigned a[4] = {p0[2 * k16], p1[2 * k16], p0[2 * k16 + 1], p1[2 * k16 + 1]};
            #pragma unroll
            for (int j2 = 0; j2 < 8; j2++) {
                unsigned bv[2];
                // V source [s][a] = [k][n] -> trans x2
                unsigned ad = sptr(Vs + (k16 * 16 + l16) * AS_ + j2 * 8);
                ldsm2t(bv, ad);
                mma16816(acc[j2], a, bv, acc[j2]);
            }
        }
    }

    // quad-reduce den (c dimension covers all s columns)
    den0 += __shfl_xor_sync(0xFFFFFFFFu, den0, 1);
    den0 += __shfl_xor_sync(0xFFFFFFFFu, den0, 2);
    den1 += __shfl_xor_sync(0xFFFFFFFFu, den1, 1);
    den1 += __shfl_xor_sync(0xFFFFFFFFu, den1, 2);
    float inv0 = 1.f / (den0 + 1e-32f);
    float inv1 = 1.f / (den1 + 1e-32f);

    __half* op = g_o + ((size_t)(b * Q_ + q0 + wid * 16)) * D_ + h * AD_;
    #pragma unroll
    for (int j2 = 0; j2 < 8; j2++) {
        int col = j2 * 8 + 2 * c;
        __half2 h0 = __floats2half2_rn(acc[j2][0] * inv0, acc[j2][1] * inv0);
        __half2 h1 = __floats2half2_rn(acc[j2][2] * inv1, acc[j2][3] * inv1);
        *(__half2*)(op + (size_t)r * D_ + col) = h0;
        *(__half2*)(op + (size_t)(r + 8) * D_ + col) = h1;
    }
}

// ---------------------------------------------------------------------------
extern "C" void kernel_launch(void* const* d_in, const int* in_sizes, int n_in,
                              void* d_out, int out_size)
{
    const float* iQ    = (const float*)d_in[0];
    const float* iK    = (const float*)d_in[1];
    const int*   mask  = (const int*)d_in[2];       // jax bool arrives as int32
    const float* Wq    = (const float*)d_in[3];
    const float* Wkv   = (const float*)d_in[4];
    const float* Wo    = (const float*)d_in[5];
    const float* nbias = (const float*)d_in[6];
    float*       out   = (float*)d_out;

    __half *hiQ, *hiK, *hWq, *hWkv, *hWo, *rq, *kv, *o;
    cudaGetSymbolAddress((void**)&hiQ,  g_hiQ);
    cudaGetSymbolAddress((void**)&hiK,  g_hiK);
    cudaGetSymbolAddress((void**)&hWq,  g_hWq);
    cudaGetSymbolAddress((void**)&hWkv, g_hWkv);
    cudaGetSymbolAddress((void**)&hWo,  g_hWo);
    cudaGetSymbolAddress((void**)&rq,   g_rq);
    cudaGetSymbolAddress((void**)&kv,   g_kv);
    cudaGetSymbolAddress((void**)&o,    g_o);

    // mask pack + fp16 converts
    {
        size_t n16 = (size_t)B_ * Q_ * S_ / 16;
        pack_mask<<<(unsigned)((n16 + 255) / 256), 256>>>(mask);
    }
    auto conv = [&](const float* s, __half* d, size_t n) {
        size_t n8 = n / 8;
        f32_to_f16<<<(unsigned)((n8 + 255) / 256), 256>>>(s, d, n8);
    };
    conv(iQ,  hiQ,  (size_t)B_ * Q_ * D_);
    conv(iK,  hiK,  (size_t)B_ * S_ * D_);
    conv(Wq,  hWq,  (size_t)D_ * D_);
    conv(Wkv, hWkv, (size_t)2 * D_ * D_);
    conv(Wo,  hWo,  (size_t)D_ * D_);

    // 1) rq = iQ @ Wq^T  (fp16 out)
    hgemm_tn<__half><<<dim3(D_ / 128, (B_ * Q_) / 128), 256>>>(hiQ, hWq, rq,
                                                               B_ * Q_, D_, D_);
    // 2) kv = iK @ Wkv^T (fp16 out)
    hgemm_tn<__half><<<dim3(2 * D_ / 128, (B_ * S_) / 128), 256>>>(hiK, hWkv, kv,
                                                                   B_ * S_, 2 * D_, D_);
    // 3) fused attention
    attn_kernel<<<dim3(Q_ / 128, B_ * H_), 256>>>(nbias);
    // 4) out = o @ Wo^T  (fp32 out)
    hgemm_tn<float><<<dim3(D_ / 128, (B_ * Q_) / 128), 256>>>(o, hWo, out,
                                                              B_ * Q_, D_, D_);
}